// round 7
// baseline (speedup 1.0000x reference)
#include <cuda_runtime.h>

#define NN 65536
#define HH 64

typedef unsigned long long ull;

// ---- packed f32x2 helpers (Blackwell FFMA2 path; 2x FP32 FMA throughput) ----
__device__ __forceinline__ ull dup2(float a) {
    ull r; asm("mov.b64 %0, {%1,%1};" : "=l"(r) : "f"(a)); return r;
}
__device__ __forceinline__ ull pk2(float a, float b) {
    ull r; asm("mov.b64 %0, {%1,%2};" : "=l"(r) : "f"(a), "f"(b)); return r;
}
__device__ __forceinline__ float2 up2(ull a) {
    float x, y; asm("mov.b64 {%0,%1}, %2;" : "=f"(x), "=f"(y) : "l"(a));
    return make_float2(x, y);
}
__device__ __forceinline__ ull f2fma(ull a, ull b, ull c) {
    ull d; asm("fma.rn.f32x2 %0, %1, %2, %3;" : "=l"(d) : "l"(a), "l"(b), "l"(c));
    return d;
}
__device__ __forceinline__ ull f2add(ull a, ull b) {
    ull d; asm("add.rn.f32x2 %0, %1, %2;" : "=l"(d) : "l"(a), "l"(b));
    return d;
}

// scratch (static device array: allowed; no runtime allocation)
__device__ float g_out[NN * HH];   // aggregated node features + residual

// ============================================================================
// Kernel 1: fused message + single-pass softmax + weighted aggregate + residual
// warp per node; lane l owns channels (2l, 2l+1) as one f32x2 pair.
// W_edge entirely in registers. ALL 16 x[src] gathers are issued up front
// (MLP=16) so L2 latency overlaps the 256-FFMA2 body.
// Edge ids for node n are exactly [16n, 16n+16) (nbr is arange).
// ============================================================================
__global__ void __launch_bounds__(256, 2) k_msg(
    const float* __restrict__ x, const float* __restrict__ ea,
    const float* __restrict__ We, const int* __restrict__ srcIdx)
{
    int t = threadIdx.x;
    int l = t & 31;
    int n = (blockIdx.x << 3) + (t >> 5);

    const ull* We2 = (const ull*)We;
    ull w[16];
    #pragma unroll
    for (int d = 0; d < 16; d++) w[d] = __ldg(We2 + d * 32 + l);

    const ull* x2 = (const ull*)x;
    const int4* sidx = (const int4*)(srcIdx + n * 16);
    int4 s0 = __ldg(sidx + 0), s1 = __ldg(sidx + 1);
    int4 s2 = __ldg(sidx + 2), s3 = __ldg(sidx + 3);
    int se[16] = { s0.x, s0.y, s0.z, s0.w,  s1.x, s1.y, s1.z, s1.w,
                   s2.x, s2.y, s2.z, s2.w,  s3.x, s3.y, s3.z, s3.w };

    // batch all 16 gathers (each warp-row is a contiguous 256B, L2-resident)
    ull xg[16];
    #pragma unroll
    for (int k = 0; k < 16; k++)
        xg[k] = __ldg(x2 + (size_t)se[k] * 32 + l);

    const float4* a4 = (const float4*)(ea + (size_t)n * 256);

    ull num = 0ULL, den = 0ULL;

    #pragma unroll
    for (int k = 0; k < 16; k++) {
        // edge_attr row: 64B, warp-uniform (broadcast) loads
        float4 a0 = __ldg(a4 + 4 * k + 0), a1 = __ldg(a4 + 4 * k + 1);
        float4 a2 = __ldg(a4 + 4 * k + 2), a3 = __ldg(a4 + 4 * k + 3);

        ull accA = xg[k], accB = 0ULL;
        accA = f2fma(dup2(a0.x), w[0],  accA);
        accB = f2fma(dup2(a0.y), w[1],  accB);
        accA = f2fma(dup2(a0.z), w[2],  accA);
        accB = f2fma(dup2(a0.w), w[3],  accB);
        accA = f2fma(dup2(a1.x), w[4],  accA);
        accB = f2fma(dup2(a1.y), w[5],  accB);
        accA = f2fma(dup2(a1.z), w[6],  accA);
        accB = f2fma(dup2(a1.w), w[7],  accB);
        accA = f2fma(dup2(a2.x), w[8],  accA);
        accB = f2fma(dup2(a2.y), w[9],  accB);
        accA = f2fma(dup2(a2.z), w[10], accA);
        accB = f2fma(dup2(a2.w), w[11], accB);
        accA = f2fma(dup2(a3.x), w[12], accA);
        accB = f2fma(dup2(a3.y), w[13], accB);
        accA = f2fma(dup2(a3.z), w[14], accA);
        accB = f2fma(dup2(a3.w), w[15], accB);

        float2 m = up2(f2add(accA, accB));
        m.x = fmaxf(m.x, 0.0f) + 1e-7f;
        m.y = fmaxf(m.y, 0.0f) + 1e-7f;
        ull ev = pk2(__expf(m.x), __expf(m.y));
        den = f2add(den, ev);
        num = f2fma(pk2(m.x, m.y), ev, num);
    }

    float2 dn = up2(den), nm = up2(num);
    float2 xn = up2(__ldg(x2 + (size_t)n * 32 + l));
    float o0 = __fdividef(nm.x, dn.x + 1e-16f) + xn.x;
    float o1 = __fdividef(nm.y, dn.y + 1e-16f) + xn.y;
    ((float2*)g_out)[n * 32 + l] = make_float2(o0, o1);
}

// ============================================================================
// Kernel 2: fused MLP  y = relu(BN(out @ W1)) @ W2
// 4 threads per node (lane: ni=l&7 node-in-warp, jq=l>>3 j-quarter).
// Each thread: layer1 over its 32 j (16 jpairs, ha[16]=32 regs), BN+ReLU,
// then a full-width layer2 partial (yac[32]=64 regs). The 4 jq partials are
// reduced IN-REGISTER via shfl_xor butterfly (lanes 8,16); lane group jq==0
// writes the final row. ~110 live regs -> __launch_bounds__(256,2) -> 128-reg
// cap -> 2 blocks/SM -> 16 warps/SM (vs 8 before).
// ============================================================================
__global__ void __launch_bounds__(256, 2) k_mlp(
    const float* __restrict__ W1, const float* __restrict__ W2,
    const float* __restrict__ gamma, const float* __restrict__ beta,
    const float* __restrict__ mean, const float* __restrict__ var,
    float* __restrict__ y)
{
    extern __shared__ ull sm[];
    ull* sW1 = sm;            // [64 c][64 jpair]  (32 KB)
    ull* sW2 = sm + 4096;     // [128 j][32 cpair] (32 KB)
    ull* sS  = sm + 8192;     // folded BN scale (64 pairs)
    ull* sB  = sm + 8256;     // folded BN shift

    int t = threadIdx.x;

    const ulonglong2* w1v = (const ulonglong2*)W1;
    const ulonglong2* w2v = (const ulonglong2*)W2;
    ulonglong2* d1 = (ulonglong2*)sW1;
    ulonglong2* d2 = (ulonglong2*)sW2;
    #pragma unroll
    for (int i = 0; i < 8; i++) {
        d1[t + 256 * i] = __ldg(w1v + t + 256 * i);
        d2[t + 256 * i] = __ldg(w2v + t + 256 * i);
    }
    if (t < 64) {
        float s0 = __ldg(gamma + 2 * t)     * rsqrtf(__ldg(var + 2 * t)     + 1e-5f);
        float s1 = __ldg(gamma + 2 * t + 1) * rsqrtf(__ldg(var + 2 * t + 1) + 1e-5f);
        sS[t] = pk2(s0, s1);
        sB[t] = pk2(__ldg(beta + 2 * t)     - __ldg(mean + 2 * t)     * s0,
                    __ldg(beta + 2 * t + 1) - __ldg(mean + 2 * t + 1) * s1);
    }
    __syncthreads();

    int l  = t & 31;
    int wp = t >> 5;
    int ni = l & 7;            // node within warp (8 nodes/warp)
    int jq = l >> 3;           // j-quarter 0..3
    int n  = blockIdx.x * 64 + wp * 8 + ni;
    int jpo = jq * 16;         // jpair offset: jpairs [jpo, jpo+16)

    const float4* orow = (const float4*)(g_out + (size_t)n * 64);

    // ---- layer 1: this thread's 16 jpairs (32 j) ----
    ull ha[16];
    #pragma unroll
    for (int p = 0; p < 16; p++) ha[p] = 0ULL;

    #pragma unroll
    for (int i = 0; i < 16; i++) {
        float4 o4 = __ldg(orow + i);
        float oc[4] = { o4.x, o4.y, o4.z, o4.w };
        #pragma unroll
        for (int c4 = 0; c4 < 4; c4++) {
            ull od = dup2(oc[c4]);
            const ulonglong2* wr =
                (const ulonglong2*)(sW1 + (4 * i + c4) * 64 + jpo);
            #pragma unroll
            for (int q = 0; q < 8; q++) {
                ulonglong2 ww = wr[q];   // LDS.128
                ha[2 * q]     = f2fma(od, ww.x, ha[2 * q]);
                ha[2 * q + 1] = f2fma(od, ww.y, ha[2 * q + 1]);
            }
        }
    }

    // ---- BN + ReLU ----
    #pragma unroll
    for (int p = 0; p < 16; p++) {
        ull hb = f2fma(ha[p], sS[jpo + p], sB[jpo + p]);
        float2 hv = up2(hb);
        hv.x = fmaxf(hv.x, 0.0f);
        hv.y = fmaxf(hv.y, 0.0f);
        ha[p] = pk2(hv.x, hv.y);
    }

    // ---- layer 2 partial: full 32-cpair width from this thread's 32 j ----
    ull yac[32];
    #pragma unroll
    for (int p = 0; p < 32; p++) yac[p] = 0ULL;

    #pragma unroll
    for (int p = 0; p < 16; p++) {
        float2 hv = up2(ha[p]);
        ull e0 = dup2(hv.x), e1 = dup2(hv.y);
        const ulonglong2* r0 = (const ulonglong2*)(sW2 + (jq * 32 + 2 * p) * 32);
        const ulonglong2* r1 = r0 + 16;
        #pragma unroll
        for (int q = 0; q < 16; q++) {
            ulonglong2 aa = r0[q], bb = r1[q];
            yac[2 * q]     = f2fma(e0, aa.x, yac[2 * q]);
            yac[2 * q + 1] = f2fma(e0, aa.y, yac[2 * q + 1]);
            yac[2 * q]     = f2fma(e1, bb.x, yac[2 * q]);
            yac[2 * q + 1] = f2fma(e1, bb.y, yac[2 * q + 1]);
        }
    }

    // ---- in-register butterfly reduction across the 4 jq groups ----
    #pragma unroll
    for (int p = 0; p < 32; p++) {
        yac[p] = f2add(yac[p], __shfl_xor_sync(0xFFFFFFFFu, yac[p], 8));
        yac[p] = f2add(yac[p], __shfl_xor_sync(0xFFFFFFFFu, yac[p], 16));
    }

    if (jq == 0) {
        ulonglong2* yrow = (ulonglong2*)(y + (size_t)n * 64);
        #pragma unroll
        for (int q = 0; q < 16; q++)
            yrow[q] = make_ulonglong2(yac[2 * q], yac[2 * q + 1]);
    }
}

// ============================================================================
extern "C" void kernel_launch(void* const* d_in, const int* in_sizes, int n_in,
                              void* d_out, int out_size)
{
    const float* x     = (const float*)d_in[0];
    const float* ea    = (const float*)d_in[1];
    const float* We    = (const float*)d_in[2];
    const float* W1    = (const float*)d_in[3];
    const float* W2    = (const float*)d_in[4];
    const float* gamma = (const float*)d_in[5];
    const float* beta  = (const float*)d_in[6];
    const float* mean  = (const float*)d_in[7];
    const float* var   = (const float*)d_in[8];
    const int*   eidx  = (const int*)d_in[9];   // row 0 = src
    float* y = (float*)d_out;

    (void)in_sizes; (void)n_in; (void)out_size;

    // cudaFuncSetAttribute is not a stream-associated op: safe under capture,
    // idempotent, deterministic.
    const int MLP_SMEM = (4096 + 4096 + 64 + 64) * 8;   // 66560 B
    cudaFuncSetAttribute(k_mlp, cudaFuncAttributeMaxDynamicSharedMemorySize,
                         MLP_SMEM);

    k_msg<<<NN / 8, 256>>>(x, ea, We, eidx);
    k_mlp<<<NN / 64, 256, MLP_SMEM>>>(W1, W2, gamma, beta, mean, var, y);
}

// round 10
// speedup vs baseline: 1.2222x; 1.2222x over previous
#include <cuda_runtime.h>

#define NN 65536
#define HH 64

typedef unsigned long long ull;

// ---- packed f32x2 helpers (Blackwell FFMA2 path; 2x FP32 FMA throughput) ----
__device__ __forceinline__ ull dup2(float a) {
    ull r; asm("mov.b64 %0, {%1,%1};" : "=l"(r) : "f"(a)); return r;
}
__device__ __forceinline__ ull pk2(float a, float b) {
    ull r; asm("mov.b64 %0, {%1,%2};" : "=l"(r) : "f"(a), "f"(b)); return r;
}
__device__ __forceinline__ float2 up2(ull a) {
    float x, y; asm("mov.b64 {%0,%1}, %2;" : "=f"(x), "=f"(y) : "l"(a));
    return make_float2(x, y);
}
__device__ __forceinline__ ull f2fma(ull a, ull b, ull c) {
    ull d; asm("fma.rn.f32x2 %0, %1, %2, %3;" : "=l"(d) : "l"(a), "l"(b), "l"(c));
    return d;
}
__device__ __forceinline__ ull f2add(ull a, ull b) {
    ull d; asm("add.rn.f32x2 %0, %1, %2;" : "=l"(d) : "l"(a), "l"(b));
    return d;
}

// scratch (static device array: allowed; no runtime allocation)
__device__ float g_out[NN * HH];   // aggregated node features + residual

// ============================================================================
// Kernel 1: fused message + single-pass softmax + weighted aggregate + residual
// warp per node; lane l owns channels (2l, 2l+1) as one f32x2 pair.
// W_edge entirely in registers. ALL 16 x[src] gathers are issued up front
// (MLP=16) so L2 latency overlaps the 256-FFMA2 body.
// Edge ids for node n are exactly [16n, 16n+16) (nbr is arange).
// ============================================================================
__global__ void __launch_bounds__(256, 2) k_msg(
    const float* __restrict__ x, const float* __restrict__ ea,
    const float* __restrict__ We, const int* __restrict__ srcIdx)
{
    int t = threadIdx.x;
    int l = t & 31;
    int n = (blockIdx.x << 3) + (t >> 5);

    const ull* We2 = (const ull*)We;
    ull w[16];
    #pragma unroll
    for (int d = 0; d < 16; d++) w[d] = __ldg(We2 + d * 32 + l);

    const ull* x2 = (const ull*)x;
    const int4* sidx = (const int4*)(srcIdx + n * 16);
    int4 s0 = __ldg(sidx + 0), s1 = __ldg(sidx + 1);
    int4 s2 = __ldg(sidx + 2), s3 = __ldg(sidx + 3);
    int se[16] = { s0.x, s0.y, s0.z, s0.w,  s1.x, s1.y, s1.z, s1.w,
                   s2.x, s2.y, s2.z, s2.w,  s3.x, s3.y, s3.z, s3.w };

    // batch all 16 gathers (each warp-row is a contiguous 256B, L2-resident)
    ull xg[16];
    #pragma unroll
    for (int k = 0; k < 16; k++)
        xg[k] = __ldg(x2 + (size_t)se[k] * 32 + l);

    const float4* a4 = (const float4*)(ea + (size_t)n * 256);

    ull num = 0ULL, den = 0ULL;

    #pragma unroll
    for (int k = 0; k < 16; k++) {
        // edge_attr row: 64B, warp-uniform (broadcast) loads
        float4 a0 = __ldg(a4 + 4 * k + 0), a1 = __ldg(a4 + 4 * k + 1);
        float4 a2 = __ldg(a4 + 4 * k + 2), a3 = __ldg(a4 + 4 * k + 3);

        ull accA = xg[k], accB = 0ULL;
        accA = f2fma(dup2(a0.x), w[0],  accA);
        accB = f2fma(dup2(a0.y), w[1],  accB);
        accA = f2fma(dup2(a0.z), w[2],  accA);
        accB = f2fma(dup2(a0.w), w[3],  accB);
        accA = f2fma(dup2(a1.x), w[4],  accA);
        accB = f2fma(dup2(a1.y), w[5],  accB);
        accA = f2fma(dup2(a1.z), w[6],  accA);
        accB = f2fma(dup2(a1.w), w[7],  accB);
        accA = f2fma(dup2(a2.x), w[8],  accA);
        accB = f2fma(dup2(a2.y), w[9],  accB);
        accA = f2fma(dup2(a2.z), w[10], accA);
        accB = f2fma(dup2(a2.w), w[11], accB);
        accA = f2fma(dup2(a3.x), w[12], accA);
        accB = f2fma(dup2(a3.y), w[13], accB);
        accA = f2fma(dup2(a3.z), w[14], accA);
        accB = f2fma(dup2(a3.w), w[15], accB);

        float2 m = up2(f2add(accA, accB));
        m.x = fmaxf(m.x, 0.0f) + 1e-7f;
        m.y = fmaxf(m.y, 0.0f) + 1e-7f;
        ull ev = pk2(__expf(m.x), __expf(m.y));
        den = f2add(den, ev);
        num = f2fma(pk2(m.x, m.y), ev, num);
    }

    float2 dn = up2(den), nm = up2(num);
    float2 xn = up2(__ldg(x2 + (size_t)n * 32 + l));
    float o0 = __fdividef(nm.x, dn.x + 1e-16f) + xn.x;
    float o1 = __fdividef(nm.y, dn.y + 1e-16f) + xn.y;
    ((float2*)g_out)[n * 32 + l] = make_float2(o0, o1);
}

// ============================================================================
// Kernel 2: fused MLP  y = relu(BN(out @ W1)) @ W2
// 2 threads per node, jh split ACROSS warps (t>>7) so every weight LDS is a
// warp-uniform broadcast (1 wavefront). Layer2 runs as TWO sequential c-half
// passes with only yac[16] live (peak regs ~115 < 128) so
// __launch_bounds__(256,2) gets 2 blocks/SM = 16 warps (vs 8 in round 6).
// jh partials combine through global y (disjoint addresses per pass).
// ============================================================================
__global__ void __launch_bounds__(256, 2) k_mlp(
    const float* __restrict__ W1, const float* __restrict__ W2,
    const float* __restrict__ gamma, const float* __restrict__ beta,
    const float* __restrict__ mean, const float* __restrict__ var,
    float* y)
{
    extern __shared__ ull sm[];
    ull* sW1 = sm;            // [64 c][64 jpair]  (32 KB)
    ull* sW2 = sm + 4096;     // [128 j][32 cpair] (32 KB)
    ull* sS  = sm + 8192;     // folded BN scale (64 pairs)
    ull* sB  = sm + 8256;     // folded BN shift

    int t = threadIdx.x;

    const ulonglong2* w1v = (const ulonglong2*)W1;
    const ulonglong2* w2v = (const ulonglong2*)W2;
    ulonglong2* d1 = (ulonglong2*)sW1;
    ulonglong2* d2 = (ulonglong2*)sW2;
    #pragma unroll
    for (int i = 0; i < 8; i++) {
        d1[t + 256 * i] = __ldg(w1v + t + 256 * i);
        d2[t + 256 * i] = __ldg(w2v + t + 256 * i);
    }
    if (t < 64) {
        float s0 = __ldg(gamma + 2 * t)     * rsqrtf(__ldg(var + 2 * t)     + 1e-5f);
        float s1 = __ldg(gamma + 2 * t + 1) * rsqrtf(__ldg(var + 2 * t + 1) + 1e-5f);
        sS[t] = pk2(s0, s1);
        sB[t] = pk2(__ldg(beta + 2 * t)     - __ldg(mean + 2 * t)     * s0,
                    __ldg(beta + 2 * t + 1) - __ldg(mean + 2 * t + 1) * s1);
    }
    __syncthreads();

    int h  = t & 127;          // node within block
    int jh = t >> 7;           // 0 or 1: which j-half this thread owns
    int n  = blockIdx.x * 128 + h;
    int joff = jh * 32;        // jpair offset

    const float4* orow = (const float4*)(g_out + (size_t)n * 64);

    // ---- layer 1 (this thread's 32 jpairs = 64 j) ----
    ull ha[32];
    #pragma unroll
    for (int p = 0; p < 32; p++) ha[p] = 0ULL;

    #pragma unroll
    for (int i = 0; i < 16; i++) {
        float4 o4 = __ldg(orow + i);
        float oc[4] = { o4.x, o4.y, o4.z, o4.w };
        #pragma unroll
        for (int c4 = 0; c4 < 4; c4++) {
            ull od = dup2(oc[c4]);
            const ulonglong2* wr =
                (const ulonglong2*)(sW1 + (4 * i + c4) * 64 + joff);
            #pragma unroll
            for (int q = 0; q < 16; q++) {
                ulonglong2 ww = wr[q];   // LDS.128 warp-uniform broadcast
                ha[2 * q]     = f2fma(od, ww.x, ha[2 * q]);
                ha[2 * q + 1] = f2fma(od, ww.y, ha[2 * q + 1]);
            }
        }
    }

    // ---- BN + ReLU ----
    #pragma unroll
    for (int p = 0; p < 32; p++) {
        ull hb = f2fma(ha[p], sS[joff + p], sB[joff + p]);
        float2 hv = up2(hb);
        hv.x = fmaxf(hv.x, 0.0f);
        hv.y = fmaxf(hv.y, 0.0f);
        ha[p] = pk2(hv.x, hv.y);
    }

    // ---- layer 2 in two sequential c-half passes (yac[16] live at a time) ----
    ulonglong2* yrow = (ulonglong2*)(y + (size_t)n * 64);

    #pragma unroll
    for (int chalf = 0; chalf < 2; chalf++) {
        const int co = chalf * 16;   // cpair offset of this pass

        ull yac[16];
        #pragma unroll
        for (int p = 0; p < 16; p++) yac[p] = 0ULL;

        #pragma unroll
        for (int p = 0; p < 32; p++) {
            float2 hv = up2(ha[p]);
            ull e0 = dup2(hv.x), e1 = dup2(hv.y);
            int j0 = 64 * jh + 2 * p;
            const ulonglong2* r0 = (const ulonglong2*)(sW2 + j0 * 32 + co);
            const ulonglong2* r1 = r0 + 16;
            #pragma unroll
            for (int q = 0; q < 8; q++) {
                ulonglong2 aa = r0[q], bb = r1[q];
                yac[2 * q]     = f2fma(e0, aa.x, yac[2 * q]);
                yac[2 * q + 1] = f2fma(e0, aa.y, yac[2 * q + 1]);
                yac[2 * q]     = f2fma(e1, bb.x, yac[2 * q]);
                yac[2 * q + 1] = f2fma(e1, bb.y, yac[2 * q + 1]);
            }
        }

        // combine jh partials through y (addresses disjoint across passes)
        if (jh == 1) {
            #pragma unroll
            for (int q = 0; q < 8; q++)
                yrow[co / 2 + q] = make_ulonglong2(yac[2 * q], yac[2 * q + 1]);
        }
        __syncthreads();   // global-write visibility within the block
        if (jh == 0) {
            #pragma unroll
            for (int q = 0; q < 8; q++) {
                ulonglong2 v = yrow[co / 2 + q];
                yrow[co / 2 + q] =
                    make_ulonglong2(f2add(yac[2 * q],     v.x),
                                    f2add(yac[2 * q + 1], v.y));
            }
        }
    }
}

// ============================================================================
extern "C" void kernel_launch(void* const* d_in, const int* in_sizes, int n_in,
                              void* d_out, int out_size)
{
    const float* x     = (const float*)d_in[0];
    const float* ea    = (const float*)d_in[1];
    const float* We    = (const float*)d_in[2];
    const float* W1    = (const float*)d_in[3];
    const float* W2    = (const float*)d_in[4];
    const float* gamma = (const float*)d_in[5];
    const float* beta  = (const float*)d_in[6];
    const float* mean  = (const float*)d_in[7];
    const float* var   = (const float*)d_in[8];
    const int*   eidx  = (const int*)d_in[9];   // row 0 = src
    float* y = (float*)d_out;

    (void)in_sizes; (void)n_in; (void)out_size;

    // cudaFuncSetAttribute is not a stream-associated op: safe under capture,
    // idempotent, deterministic.
    const int MLP_SMEM = (4096 + 4096 + 64 + 64) * 8;   // 66560 B
    cudaFuncSetAttribute(k_mlp, cudaFuncAttributeMaxDynamicSharedMemorySize,
                         MLP_SMEM);

    k_msg<<<NN / 8, 256>>>(x, ea, We, eidx);
    k_mlp<<<NN / 128, 256, MLP_SMEM>>>(W1, W2, gamma, beta, mean, var, y);
}

// round 12
// speedup vs baseline: 1.5402x; 1.2602x over previous
#include <cuda_runtime.h>

#define NN 65536
#define HH 64

typedef unsigned long long ull;
typedef unsigned int u32;

// ---- packed f32x2 helpers (Blackwell FFMA2 path; 2x FP32 FMA throughput) ----
__device__ __forceinline__ ull dup2(float a) {
    ull r; asm("mov.b64 %0, {%1,%1};" : "=l"(r) : "f"(a)); return r;
}
__device__ __forceinline__ ull pk2(float a, float b) {
    ull r; asm("mov.b64 %0, {%1,%2};" : "=l"(r) : "f"(a), "f"(b)); return r;
}
__device__ __forceinline__ float2 up2(ull a) {
    float x, y; asm("mov.b64 {%0,%1}, %2;" : "=f"(x), "=f"(y) : "l"(a));
    return make_float2(x, y);
}
__device__ __forceinline__ ull f2fma(ull a, ull b, ull c) {
    ull d; asm("fma.rn.f32x2 %0, %1, %2, %3;" : "=l"(d) : "l"(a), "l"(b), "l"(c));
    return d;
}
__device__ __forceinline__ ull f2add(ull a, ull b) {
    ull d; asm("add.rn.f32x2 %0, %1, %2;" : "=l"(d) : "l"(a), "l"(b));
    return d;
}

// scratch (static device array: allowed; no runtime allocation)
__device__ float g_out[NN * HH];   // aggregated node features + residual

// ============================================================================
// Kernel 1: fused message + single-pass softmax + weighted aggregate + residual
// warp per node; lane l owns channels (2l, 2l+1) as one f32x2 pair.
// W_edge entirely in registers. The node's full 1KB edge_attr row is staged
// into SMEM via cp.async (2 warp-instructions) BEFORE the w/sidx/x loads so
// DRAM latency overlaps them; the compute loop reads ea via cheap uniform
// LDS broadcasts instead of 64 long-latency uniform LDGs.
// Edge ids for node n are exactly [16n, 16n+16) (nbr is arange).
// ============================================================================
__global__ void __launch_bounds__(256, 2) k_msg(
    const float* __restrict__ x, const float* __restrict__ ea,
    const float* __restrict__ We, const int* __restrict__ srcIdx)
{
    __shared__ float4 sEA[8][64];   // 8 warps x 1KB

    int t = threadIdx.x;
    int l = t & 31;
    int wid = t >> 5;
    int n = (blockIdx.x << 3) + wid;

    // ---- stage ea[node] (1KB) via cp.async: 2 x 16B per lane ----
    {
        const float4* easrc = (const float4*)(ea + (size_t)n * 256);
        u32 dst = (u32)__cvta_generic_to_shared(&sEA[wid][l]);
        asm volatile("cp.async.ca.shared.global [%0], [%1], 16;\n"
                     :: "r"(dst), "l"(easrc + l));
        asm volatile("cp.async.ca.shared.global [%0], [%1], 16;\n"
                     :: "r"(dst + 512), "l"(easrc + l + 32));
        asm volatile("cp.async.commit_group;\n");
    }

    // ---- W_edge[d][2l..2l+1] in registers, reused across all 16 edges ----
    const ull* We2 = (const ull*)We;
    ull w[16];
    #pragma unroll
    for (int d = 0; d < 16; d++) w[d] = __ldg(We2 + d * 32 + l);

    const ull* x2 = (const ull*)x;
    const int4* sidx = (const int4*)(srcIdx + n * 16);
    int4 s0 = __ldg(sidx + 0), s1 = __ldg(sidx + 1);
    int4 s2 = __ldg(sidx + 2), s3 = __ldg(sidx + 3);
    int se[16] = { s0.x, s0.y, s0.z, s0.w,  s1.x, s1.y, s1.z, s1.w,
                   s2.x, s2.y, s2.z, s2.w,  s3.x, s3.y, s3.z, s3.w };

    // batch all 16 x gathers (each warp-row is a contiguous 256B, L2-resident)
    ull xg[16];
    #pragma unroll
    for (int k = 0; k < 16; k++)
        xg[k] = __ldg(x2 + (size_t)se[k] * 32 + l);

    // residual row (also L2-latency-overlapped)
    ull xres = __ldg(x2 + (size_t)n * 32 + l);

    // ---- wait for ea staging, make lane-written smem visible warp-wide ----
    asm volatile("cp.async.wait_group 0;\n");
    __syncwarp();

    const float4* av = sEA[wid];
    ull num = 0ULL, den = 0ULL;

    #pragma unroll
    for (int k = 0; k < 16; k++) {
        // edge_attr row: 64B, warp-uniform LDS broadcasts (cheap)
        float4 a0 = av[4 * k + 0], a1 = av[4 * k + 1];
        float4 a2 = av[4 * k + 2], a3 = av[4 * k + 3];

        ull accA = xg[k], accB = 0ULL;
        accA = f2fma(dup2(a0.x), w[0],  accA);
        accB = f2fma(dup2(a0.y), w[1],  accB);
        accA = f2fma(dup2(a0.z), w[2],  accA);
        accB = f2fma(dup2(a0.w), w[3],  accB);
        accA = f2fma(dup2(a1.x), w[4],  accA);
        accB = f2fma(dup2(a1.y), w[5],  accB);
        accA = f2fma(dup2(a1.z), w[6],  accA);
        accB = f2fma(dup2(a1.w), w[7],  accB);
        accA = f2fma(dup2(a2.x), w[8],  accA);
        accB = f2fma(dup2(a2.y), w[9],  accB);
        accA = f2fma(dup2(a2.z), w[10], accA);
        accB = f2fma(dup2(a2.w), w[11], accB);
        accA = f2fma(dup2(a3.x), w[12], accA);
        accB = f2fma(dup2(a3.y), w[13], accB);
        accA = f2fma(dup2(a3.z), w[14], accA);
        accB = f2fma(dup2(a3.w), w[15], accB);

        float2 m = up2(f2add(accA, accB));
        m.x = fmaxf(m.x, 0.0f) + 1e-7f;
        m.y = fmaxf(m.y, 0.0f) + 1e-7f;
        ull ev = pk2(__expf(m.x), __expf(m.y));
        den = f2add(den, ev);
        num = f2fma(pk2(m.x, m.y), ev, num);
    }

    float2 dn = up2(den), nm = up2(num);
    float2 xn = up2(xres);
    float o0 = __fdividef(nm.x, dn.x + 1e-16f) + xn.x;
    float o1 = __fdividef(nm.y, dn.y + 1e-16f) + xn.y;
    ((float2*)g_out)[n * 32 + l] = make_float2(o0, o1);
}

// ============================================================================
// Kernel 2: fused MLP  y = relu(BN(out @ W1)) @ W2
// 2 threads per node, jh split ACROSS warps (t>>7) so every weight LDS is a
// warp-uniform broadcast (1 wavefront). Layer2 runs as TWO sequential c-half
// passes with only yac[16] live (peak regs ~115 < 128) so
// __launch_bounds__(256,2) gets 2 blocks/SM = 16 warps.
// jh partials combine through global y (disjoint addresses per pass).
// ============================================================================
__global__ void __launch_bounds__(256, 2) k_mlp(
    const float* __restrict__ W1, const float* __restrict__ W2,
    const float* __restrict__ gamma, const float* __restrict__ beta,
    const float* __restrict__ mean, const float* __restrict__ var,
    float* y)
{
    extern __shared__ ull sm[];
    ull* sW1 = sm;            // [64 c][64 jpair]  (32 KB)
    ull* sW2 = sm + 4096;     // [128 j][32 cpair] (32 KB)
    ull* sS  = sm + 8192;     // folded BN scale (64 pairs)
    ull* sB  = sm + 8256;     // folded BN shift

    int t = threadIdx.x;

    const ulonglong2* w1v = (const ulonglong2*)W1;
    const ulonglong2* w2v = (const ulonglong2*)W2;
    ulonglong2* d1 = (ulonglong2*)sW1;
    ulonglong2* d2 = (ulonglong2*)sW2;
    #pragma unroll
    for (int i = 0; i < 8; i++) {
        d1[t + 256 * i] = __ldg(w1v + t + 256 * i);
        d2[t + 256 * i] = __ldg(w2v + t + 256 * i);
    }
    if (t < 64) {
        float s0 = __ldg(gamma + 2 * t)     * rsqrtf(__ldg(var + 2 * t)     + 1e-5f);
        float s1 = __ldg(gamma + 2 * t + 1) * rsqrtf(__ldg(var + 2 * t + 1) + 1e-5f);
        sS[t] = pk2(s0, s1);
        sB[t] = pk2(__ldg(beta + 2 * t)     - __ldg(mean + 2 * t)     * s0,
                    __ldg(beta + 2 * t + 1) - __ldg(mean + 2 * t + 1) * s1);
    }
    __syncthreads();

    int h  = t & 127;          // node within block
    int jh = t >> 7;           // 0 or 1: which j-half this thread owns
    int n  = blockIdx.x * 128 + h;
    int joff = jh * 32;        // jpair offset

    const float4* orow = (const float4*)(g_out + (size_t)n * 64);

    // ---- layer 1 (this thread's 32 jpairs = 64 j) ----
    ull ha[32];
    #pragma unroll
    for (int p = 0; p < 32; p++) ha[p] = 0ULL;

    #pragma unroll
    for (int i = 0; i < 16; i++) {
        float4 o4 = __ldg(orow + i);
        float oc[4] = { o4.x, o4.y, o4.z, o4.w };
        #pragma unroll
        for (int c4 = 0; c4 < 4; c4++) {
            ull od = dup2(oc[c4]);
            const ulonglong2* wr =
                (const ulonglong2*)(sW1 + (4 * i + c4) * 64 + joff);
            #pragma unroll
            for (int q = 0; q < 16; q++) {
                ulonglong2 ww = wr[q];   // LDS.128 warp-uniform broadcast
                ha[2 * q]     = f2fma(od, ww.x, ha[2 * q]);
                ha[2 * q + 1] = f2fma(od, ww.y, ha[2 * q + 1]);
            }
        }
    }

    // ---- BN + ReLU ----
    #pragma unroll
    for (int p = 0; p < 32; p++) {
        ull hb = f2fma(ha[p], sS[joff + p], sB[joff + p]);
        float2 hv = up2(hb);
        hv.x = fmaxf(hv.x, 0.0f);
        hv.y = fmaxf(hv.y, 0.0f);
        ha[p] = pk2(hv.x, hv.y);
    }

    // ---- layer 2 in two sequential c-half passes (yac[16] live at a time) ----
    ulonglong2* yrow = (ulonglong2*)(y + (size_t)n * 64);

    #pragma unroll
    for (int chalf = 0; chalf < 2; chalf++) {
        const int co = chalf * 16;   // cpair offset of this pass

        ull yac[16];
        #pragma unroll
        for (int p = 0; p < 16; p++) yac[p] = 0ULL;

        #pragma unroll
        for (int p = 0; p < 32; p++) {
            float2 hv = up2(ha[p]);
            ull e0 = dup2(hv.x), e1 = dup2(hv.y);
            int j0 = 64 * jh + 2 * p;
            const ulonglong2* r0 = (const ulonglong2*)(sW2 + j0 * 32 + co);
            const ulonglong2* r1 = r0 + 16;
            #pragma unroll
            for (int q = 0; q < 8; q++) {
                ulonglong2 aa = r0[q], bb = r1[q];
                yac[2 * q]     = f2fma(e0, aa.x, yac[2 * q]);
                yac[2 * q + 1] = f2fma(e0, aa.y, yac[2 * q + 1]);
                yac[2 * q]     = f2fma(e1, bb.x, yac[2 * q]);
                yac[2 * q + 1] = f2fma(e1, bb.y, yac[2 * q + 1]);
            }
        }

        // combine jh partials through y (addresses disjoint across passes)
        if (jh == 1) {
            #pragma unroll
            for (int q = 0; q < 8; q++)
                yrow[co / 2 + q] = make_ulonglong2(yac[2 * q], yac[2 * q + 1]);
        }
        __syncthreads();   // global-write visibility within the block
        if (jh == 0) {
            #pragma unroll
            for (int q = 0; q < 8; q++) {
                ulonglong2 v = yrow[co / 2 + q];
                yrow[co / 2 + q] =
                    make_ulonglong2(f2add(yac[2 * q],     v.x),
                                    f2add(yac[2 * q + 1], v.y));
            }
        }
    }
}

// ============================================================================
extern "C" void kernel_launch(void* const* d_in, const int* in_sizes, int n_in,
                              void* d_out, int out_size)
{
    const float* x     = (const float*)d_in[0];
    const float* ea    = (const float*)d_in[1];
    const float* We    = (const float*)d_in[2];
    const float* W1    = (const float*)d_in[3];
    const float* W2    = (const float*)d_in[4];
    const float* gamma = (const float*)d_in[5];
    const float* beta  = (const float*)d_in[6];
    const float* mean  = (const float*)d_in[7];
    const float* var   = (const float*)d_in[8];
    const int*   eidx  = (const int*)d_in[9];   // row 0 = src
    float* y = (float*)d_out;

    (void)in_sizes; (void)n_in; (void)out_size;

    // cudaFuncSetAttribute is not a stream-associated op: safe under capture,
    // idempotent, deterministic.
    const int MLP_SMEM = (4096 + 4096 + 64 + 64) * 8;   // 66560 B
    cudaFuncSetAttribute(k_mlp, cudaFuncAttributeMaxDynamicSharedMemorySize,
                         MLP_SMEM);

    k_msg<<<NN / 8, 256>>>(x, ea, We, eidx);
    k_mlp<<<NN / 128, 256, MLP_SMEM>>>(W1, W2, gamma, beta, mean, var, y);
}

// round 14
// speedup vs baseline: 1.7403x; 1.1299x over previous
#include <cuda_runtime.h>

#define NN 65536
#define HH 64

typedef unsigned long long ull;
typedef unsigned int u32;

// ---- packed f32x2 helpers (Blackwell FFMA2 path; 2x FP32 FMA throughput) ----
__device__ __forceinline__ ull dup2(float a) {
    ull r; asm("mov.b64 %0, {%1,%1};" : "=l"(r) : "f"(a)); return r;
}
__device__ __forceinline__ ull pk2(float a, float b) {
    ull r; asm("mov.b64 %0, {%1,%2};" : "=l"(r) : "f"(a), "f"(b)); return r;
}
__device__ __forceinline__ float2 up2(ull a) {
    float x, y; asm("mov.b64 {%0,%1}, %2;" : "=f"(x), "=f"(y) : "l"(a));
    return make_float2(x, y);
}
__device__ __forceinline__ ull f2fma(ull a, ull b, ull c) {
    ull d; asm("fma.rn.f32x2 %0, %1, %2, %3;" : "=l"(d) : "l"(a), "l"(b), "l"(c));
    return d;
}
__device__ __forceinline__ ull f2add(ull a, ull b) {
    ull d; asm("add.rn.f32x2 %0, %1, %2;" : "=l"(d) : "l"(a), "l"(b));
    return d;
}
__device__ __forceinline__ ull f2relu(ull a) {
    float2 v = up2(a);
    return pk2(fmaxf(v.x, 0.0f), fmaxf(v.y, 0.0f));
}

// scratch (static device arrays: allowed; no runtime allocation)
__device__ float g_out[NN * HH];        // aggregated node features + residual
__device__ float g_h[NN * 2 * HH];      // hidden activations (relu(BN(.)))

// ============================================================================
// Kernel 1: fused message + single-pass softmax + weighted aggregate + residual
// warp per node; lane l owns channels (2l, 2l+1) as one f32x2 pair.
// W_edge in registers; node's 1KB edge_attr row staged via cp.async.
// (unchanged from round 12 — passing at ~77us)
// ============================================================================
__global__ void __launch_bounds__(256, 2) k_msg(
    const float* __restrict__ x, const float* __restrict__ ea,
    const float* __restrict__ We, const int* __restrict__ srcIdx)
{
    __shared__ float4 sEA[8][64];   // 8 warps x 1KB

    int t = threadIdx.x;
    int l = t & 31;
    int wid = t >> 5;
    int n = (blockIdx.x << 3) + wid;

    {
        const float4* easrc = (const float4*)(ea + (size_t)n * 256);
        u32 dst = (u32)__cvta_generic_to_shared(&sEA[wid][l]);
        asm volatile("cp.async.ca.shared.global [%0], [%1], 16;\n"
                     :: "r"(dst), "l"(easrc + l));
        asm volatile("cp.async.ca.shared.global [%0], [%1], 16;\n"
                     :: "r"(dst + 512), "l"(easrc + l + 32));
        asm volatile("cp.async.commit_group;\n");
    }

    const ull* We2 = (const ull*)We;
    ull w[16];
    #pragma unroll
    for (int d = 0; d < 16; d++) w[d] = __ldg(We2 + d * 32 + l);

    const ull* x2 = (const ull*)x;
    const int4* sidx = (const int4*)(srcIdx + n * 16);
    int4 s0 = __ldg(sidx + 0), s1 = __ldg(sidx + 1);
    int4 s2 = __ldg(sidx + 2), s3 = __ldg(sidx + 3);
    int se[16] = { s0.x, s0.y, s0.z, s0.w,  s1.x, s1.y, s1.z, s1.w,
                   s2.x, s2.y, s2.z, s2.w,  s3.x, s3.y, s3.z, s3.w };

    ull xg[16];
    #pragma unroll
    for (int k = 0; k < 16; k++)
        xg[k] = __ldg(x2 + (size_t)se[k] * 32 + l);

    ull xres = __ldg(x2 + (size_t)n * 32 + l);

    asm volatile("cp.async.wait_group 0;\n");
    __syncwarp();

    const float4* av = sEA[wid];
    ull num = 0ULL, den = 0ULL;

    #pragma unroll
    for (int k = 0; k < 16; k++) {
        float4 a0 = av[4 * k + 0], a1 = av[4 * k + 1];
        float4 a2 = av[4 * k + 2], a3 = av[4 * k + 3];

        ull accA = xg[k], accB = 0ULL;
        accA = f2fma(dup2(a0.x), w[0],  accA);
        accB = f2fma(dup2(a0.y), w[1],  accB);
        accA = f2fma(dup2(a0.z), w[2],  accA);
        accB = f2fma(dup2(a0.w), w[3],  accB);
        accA = f2fma(dup2(a1.x), w[4],  accA);
        accB = f2fma(dup2(a1.y), w[5],  accB);
        accA = f2fma(dup2(a1.z), w[6],  accA);
        accB = f2fma(dup2(a1.w), w[7],  accB);
        accA = f2fma(dup2(a2.x), w[8],  accA);
        accB = f2fma(dup2(a2.y), w[9],  accB);
        accA = f2fma(dup2(a2.z), w[10], accA);
        accB = f2fma(dup2(a2.w), w[11], accB);
        accA = f2fma(dup2(a3.x), w[12], accA);
        accB = f2fma(dup2(a3.y), w[13], accB);
        accA = f2fma(dup2(a3.z), w[14], accA);
        accB = f2fma(dup2(a3.w), w[15], accB);

        float2 m = up2(f2add(accA, accB));
        m.x = fmaxf(m.x, 0.0f) + 1e-7f;
        m.y = fmaxf(m.y, 0.0f) + 1e-7f;
        ull ev = pk2(__expf(m.x), __expf(m.y));
        den = f2add(den, ev);
        num = f2fma(pk2(m.x, m.y), ev, num);
    }

    float2 dn = up2(den), nm = up2(num);
    float2 xn = up2(xres);
    float o0 = __fdividef(nm.x, dn.x + 1e-16f) + xn.x;
    float o1 = __fdividef(nm.y, dn.y + 1e-16f) + xn.y;
    ((float2*)g_out)[n * 32 + l] = make_float2(o0, o1);
}

// ============================================================================
// Kernel 2a: h = relu(BN(out @ W1)) — register-tiled GEMM.
// Block: 128-node tile, 256 threads = (m = t&31: node quad, jg = t>>5: 16-j group).
// Activations staged TRANSPOSED sO[c][node]: one LDS.128 = 4 nodes' o[c].
// Weights warp-uniform (whole warp shares jg). 32 FFMA2 per 5 LDS.128.
// ============================================================================
__global__ void __launch_bounds__(256, 2) k_mlp1(
    const float* __restrict__ W1, const float* __restrict__ gamma,
    const float* __restrict__ beta, const float* __restrict__ mean,
    const float* __restrict__ var)
{
    extern __shared__ ull smA[];
    ull*   sW1 = smA;                      // [64 c][64 jpair]   32 KB
    ull*   sS  = smA + 4096;               // folded BN scale (64 jpairs)
    ull*   sB  = smA + 4160;               // folded BN shift
    float* sO  = (float*)(smA + 4224);     // [64 c][128 node]   32 KB

    int t  = threadIdx.x;
    int nb = blockIdx.x * 128;

    // stage W1 (coalesced)
    {
        const ulonglong2* w1v = (const ulonglong2*)W1;
        ulonglong2* d1 = (ulonglong2*)sW1;
        #pragma unroll
        for (int i = 0; i < 8; i++)
            d1[t + 256 * i] = __ldg(w1v + t + 256 * i);
    }
    // folded BN
    if (t < 64) {
        float s0 = __ldg(gamma + 2 * t)     * rsqrtf(__ldg(var + 2 * t)     + 1e-5f);
        float s1 = __ldg(gamma + 2 * t + 1) * rsqrtf(__ldg(var + 2 * t + 1) + 1e-5f);
        sS[t] = pk2(s0, s1);
        sB[t] = pk2(__ldg(beta + 2 * t)     - __ldg(mean + 2 * t)     * s0,
                    __ldg(beta + 2 * t + 1) - __ldg(mean + 2 * t + 1) * s1);
    }
    // stage O transposed: thread covers node (t&127), c-half (t>>7)
    {
        int n  = t & 127;
        int ch = (t >> 7) * 32;
        const float4* src = (const float4*)(g_out + (size_t)(nb + n) * 64 + ch);
        #pragma unroll
        for (int i = 0; i < 8; i++) {
            float4 v = __ldg(src + i);
            int c = ch + 4 * i;
            sO[(c + 0) * 128 + n] = v.x;
            sO[(c + 1) * 128 + n] = v.y;
            sO[(c + 2) * 128 + n] = v.z;
            sO[(c + 3) * 128 + n] = v.w;
        }
    }
    __syncthreads();

    int m  = t & 31;    // node quad: nodes 4m..4m+3
    int jg = t >> 5;    // 16-j group (jpairs jg*8..jg*8+7); warp-uniform

    ull acc[32];
    #pragma unroll
    for (int p = 0; p < 32; p++) acc[p] = 0ULL;

    #pragma unroll 8
    for (int c = 0; c < 64; c++) {
        float4 a4 = *(const float4*)(sO + c * 128 + m * 4);
        const ulonglong2* bp = (const ulonglong2*)(sW1 + c * 64 + jg * 8);
        ulonglong2 b0 = bp[0], b1 = bp[1], b2 = bp[2], b3 = bp[3];
        ull wr[8] = { b0.x, b0.y, b1.x, b1.y, b2.x, b2.y, b3.x, b3.y };
        ull ad0 = dup2(a4.x), ad1 = dup2(a4.y), ad2 = dup2(a4.z), ad3 = dup2(a4.w);
        #pragma unroll
        for (int p = 0; p < 8; p++) {
            acc[p]      = f2fma(ad0, wr[p], acc[p]);
            acc[8 + p]  = f2fma(ad1, wr[p], acc[8 + p]);
            acc[16 + p] = f2fma(ad2, wr[p], acc[16 + p]);
            acc[24 + p] = f2fma(ad3, wr[p], acc[24 + p]);
        }
    }

    // BN + ReLU + store h
    #pragma unroll
    for (int mm = 0; mm < 4; mm++) {
        ulonglong2* dst =
            (ulonglong2*)(g_h + (size_t)(nb + m * 4 + mm) * 128 + jg * 16);
        #pragma unroll
        for (int q = 0; q < 4; q++) {
            ull h0 = f2relu(f2fma(acc[mm * 8 + 2 * q],
                                  sS[jg * 8 + 2 * q], sB[jg * 8 + 2 * q]));
            ull h1 = f2relu(f2fma(acc[mm * 8 + 2 * q + 1],
                                  sS[jg * 8 + 2 * q + 1], sB[jg * 8 + 2 * q + 1]));
            dst[q] = make_ulonglong2(h0, h1);
        }
    }
}

// ============================================================================
// Kernel 2b: y = h @ W2 — register-tiled GEMM.
// Block: 128-node tile, 256 threads = (m = t&31: node quad, cg = t>>5: 8-c group).
// sH staged transposed [j][node]; weights warp-uniform. 16 FFMA2 / 3 LDS.128.
// ============================================================================
__global__ void __launch_bounds__(256, 2) k_mlp2(
    const float* __restrict__ W2, float* __restrict__ y)
{
    extern __shared__ ull smB[];
    ull*   sW2 = smB;                      // [128 j][32 cpair]  32 KB
    float* sH  = (float*)(smB + 4096);     // [128 j][128 node]  64 KB

    int t  = threadIdx.x;
    int nb = blockIdx.x * 128;

    // stage W2
    {
        const ulonglong2* w2v = (const ulonglong2*)W2;
        ulonglong2* d2 = (ulonglong2*)sW2;
        #pragma unroll
        for (int i = 0; i < 8; i++)
            d2[t + 256 * i] = __ldg(w2v + t + 256 * i);
    }
    // stage H transposed: thread covers node (t&127), j-half (t>>7)
    {
        int n  = t & 127;
        int jh = (t >> 7) * 64;
        const float4* src = (const float4*)(g_h + (size_t)(nb + n) * 128 + jh);
        #pragma unroll
        for (int i = 0; i < 16; i++) {
            float4 v = __ldg(src + i);
            int j = jh + 4 * i;
            sH[(j + 0) * 128 + n] = v.x;
            sH[(j + 1) * 128 + n] = v.y;
            sH[(j + 2) * 128 + n] = v.z;
            sH[(j + 3) * 128 + n] = v.w;
        }
    }
    __syncthreads();

    int m  = t & 31;    // node quad
    int cg = t >> 5;    // 8-c group (cpairs cg*4..cg*4+3); warp-uniform

    ull acc[16];
    #pragma unroll
    for (int p = 0; p < 16; p++) acc[p] = 0ULL;

    #pragma unroll 8
    for (int k = 0; k < 128; k++) {
        float4 a4 = *(const float4*)(sH + k * 128 + m * 4);
        const ulonglong2* bp = (const ulonglong2*)(sW2 + k * 32 + cg * 4);
        ulonglong2 b0 = bp[0], b1 = bp[1];
        ull wr[4] = { b0.x, b0.y, b1.x, b1.y };
        ull ad0 = dup2(a4.x), ad1 = dup2(a4.y), ad2 = dup2(a4.z), ad3 = dup2(a4.w);
        #pragma unroll
        for (int p = 0; p < 4; p++) {
            acc[p]      = f2fma(ad0, wr[p], acc[p]);
            acc[4 + p]  = f2fma(ad1, wr[p], acc[4 + p]);
            acc[8 + p]  = f2fma(ad2, wr[p], acc[8 + p]);
            acc[12 + p] = f2fma(ad3, wr[p], acc[12 + p]);
        }
    }

    #pragma unroll
    for (int mm = 0; mm < 4; mm++) {
        ulonglong2* dst =
            (ulonglong2*)(y + (size_t)(nb + m * 4 + mm) * 64 + cg * 8);
        dst[0] = make_ulonglong2(acc[mm * 4 + 0], acc[mm * 4 + 1]);
        dst[1] = make_ulonglong2(acc[mm * 4 + 2], acc[mm * 4 + 3]);
    }
}

// ============================================================================
extern "C" void kernel_launch(void* const* d_in, const int* in_sizes, int n_in,
                              void* d_out, int out_size)
{
    const float* x     = (const float*)d_in[0];
    const float* ea    = (const float*)d_in[1];
    const float* We    = (const float*)d_in[2];
    const float* W1    = (const float*)d_in[3];
    const float* W2    = (const float*)d_in[4];
    const float* gamma = (const float*)d_in[5];
    const float* beta  = (const float*)d_in[6];
    const float* mean  = (const float*)d_in[7];
    const float* var   = (const float*)d_in[8];
    const int*   eidx  = (const int*)d_in[9];   // row 0 = src
    float* y = (float*)d_out;

    (void)in_sizes; (void)n_in; (void)out_size;

    // cudaFuncSetAttribute is not a stream-associated op: safe under capture,
    // idempotent, deterministic.
    const int SMEM1 = (4096 + 64 + 64) * 8 + 64 * 128 * 4;   // 66560 B
    const int SMEM2 = 4096 * 8 + 128 * 128 * 4;              // 98304 B
    cudaFuncSetAttribute(k_mlp1, cudaFuncAttributeMaxDynamicSharedMemorySize,
                         SMEM1);
    cudaFuncSetAttribute(k_mlp2, cudaFuncAttributeMaxDynamicSharedMemorySize,
                         SMEM2);

    k_msg<<<NN / 8, 256>>>(x, ea, We, eidx);
    k_mlp1<<<NN / 128, 256, SMEM1>>>(W1, gamma, beta, mean, var);
    k_mlp2<<<NN / 128, 256, SMEM2>>>(W2, y);
}

// round 16
// speedup vs baseline: 2.1265x; 1.2219x over previous
#include <cuda_runtime.h>

#define NN 65536
#define HH 64

typedef unsigned long long ull;
typedef unsigned int u32;

// ---- packed f32x2 helpers (Blackwell FFMA2 path; 2x FP32 FMA throughput) ----
__device__ __forceinline__ ull dup2(float a) {
    ull r; asm("mov.b64 %0, {%1,%1};" : "=l"(r) : "f"(a)); return r;
}
__device__ __forceinline__ ull pk2(float a, float b) {
    ull r; asm("mov.b64 %0, {%1,%2};" : "=l"(r) : "f"(a), "f"(b)); return r;
}
__device__ __forceinline__ float2 up2(ull a) {
    float x, y; asm("mov.b64 {%0,%1}, %2;" : "=f"(x), "=f"(y) : "l"(a));
    return make_float2(x, y);
}
__device__ __forceinline__ ull f2fma(ull a, ull b, ull c) {
    ull d; asm("fma.rn.f32x2 %0, %1, %2, %3;" : "=l"(d) : "l"(a), "l"(b), "l"(c));
    return d;
}
__device__ __forceinline__ ull f2add(ull a, ull b) {
    ull d; asm("add.rn.f32x2 %0, %1, %2;" : "=l"(d) : "l"(a), "l"(b));
    return d;
}

// scratch (static device array: allowed; no runtime allocation)
__device__ float g_out[NN * HH];   // aggregated node features + residual

// ============================================================================
// Kernel 1: fused message + single-pass softmax + weighted aggregate + residual
// warp per node; lane l owns channels (2l, 2l+1) as one f32x2 pair.
// W_edge in registers; node's 1KB edge_attr row staged via cp.async.
// x-gathers issued in TWO 8-deep batches so fewer loads/addresses are live
// at once -> fits 85 regs -> __launch_bounds__(256,3) -> 24 warps/SM.
// ============================================================================
__global__ void __launch_bounds__(256, 3) k_msg(
    const float* __restrict__ x, const float* __restrict__ ea,
    const float* __restrict__ We, const int* __restrict__ srcIdx)
{
    __shared__ float4 sEA[8][64];   // 8 warps x 1KB

    int t = threadIdx.x;
    int l = t & 31;
    int wid = t >> 5;
    int n = (blockIdx.x << 3) + wid;

    {
        const float4* easrc = (const float4*)(ea + (size_t)n * 256);
        u32 dst = (u32)__cvta_generic_to_shared(&sEA[wid][l]);
        asm volatile("cp.async.ca.shared.global [%0], [%1], 16;\n"
                     :: "r"(dst), "l"(easrc + l));
        asm volatile("cp.async.ca.shared.global [%0], [%1], 16;\n"
                     :: "r"(dst + 512), "l"(easrc + l + 32));
        asm volatile("cp.async.commit_group;\n");
    }

    const ull* We2 = (const ull*)We;
    ull w[16];
    #pragma unroll
    for (int d = 0; d < 16; d++) w[d] = __ldg(We2 + d * 32 + l);

    const ull* x2 = (const ull*)x;
    const int4* sidx = (const int4*)(srcIdx + n * 16);

    // batch A: edges 0..7
    int4 s0 = __ldg(sidx + 0), s1 = __ldg(sidx + 1);
    int seA[8] = { s0.x, s0.y, s0.z, s0.w,  s1.x, s1.y, s1.z, s1.w };
    ull xgA[8];
    #pragma unroll
    for (int k = 0; k < 8; k++)
        xgA[k] = __ldg(x2 + (size_t)seA[k] * 32 + l);

    // batch B: edges 8..15 (issued before consuming A)
    int4 s2 = __ldg(sidx + 2), s3 = __ldg(sidx + 3);
    int seB[8] = { s2.x, s2.y, s2.z, s2.w,  s3.x, s3.y, s3.z, s3.w };
    ull xgB[8];
    #pragma unroll
    for (int k = 0; k < 8; k++)
        xgB[k] = __ldg(x2 + (size_t)seB[k] * 32 + l);

    ull xres = __ldg(x2 + (size_t)n * 32 + l);

    asm volatile("cp.async.wait_group 0;\n");
    __syncwarp();

    const float4* av = sEA[wid];
    ull num = 0ULL, den = 0ULL;

    #pragma unroll
    for (int half = 0; half < 2; half++) {
        #pragma unroll
        for (int kk = 0; kk < 8; kk++) {
            int k = half * 8 + kk;
            float4 a0 = av[4 * k + 0], a1 = av[4 * k + 1];
            float4 a2 = av[4 * k + 2], a3 = av[4 * k + 3];

            ull accA = (half == 0) ? xgA[kk] : xgB[kk];
            ull accB = 0ULL;
            accA = f2fma(dup2(a0.x), w[0],  accA);
            accB = f2fma(dup2(a0.y), w[1],  accB);
            accA = f2fma(dup2(a0.z), w[2],  accA);
            accB = f2fma(dup2(a0.w), w[3],  accB);
            accA = f2fma(dup2(a1.x), w[4],  accA);
            accB = f2fma(dup2(a1.y), w[5],  accB);
            accA = f2fma(dup2(a1.z), w[6],  accA);
            accB = f2fma(dup2(a1.w), w[7],  accB);
            accA = f2fma(dup2(a2.x), w[8],  accA);
            accB = f2fma(dup2(a2.y), w[9],  accB);
            accA = f2fma(dup2(a2.z), w[10], accA);
            accB = f2fma(dup2(a2.w), w[11], accB);
            accA = f2fma(dup2(a3.x), w[12], accA);
            accB = f2fma(dup2(a3.y), w[13], accB);
            accA = f2fma(dup2(a3.z), w[14], accA);
            accB = f2fma(dup2(a3.w), w[15], accB);

            float2 m = up2(f2add(accA, accB));
            m.x = fmaxf(m.x, 0.0f) + 1e-7f;
            m.y = fmaxf(m.y, 0.0f) + 1e-7f;
            ull ev = pk2(__expf(m.x), __expf(m.y));
            den = f2add(den, ev);
            num = f2fma(pk2(m.x, m.y), ev, num);
        }
    }

    float2 dn = up2(den), nm = up2(num);
    float2 xn = up2(xres);
    float o0 = __fdividef(nm.x, dn.x + 1e-16f) + xn.x;
    float o1 = __fdividef(nm.y, dn.y + 1e-16f) + xn.y;
    ((float2*)g_out)[n * 32 + l] = make_float2(o0, o1);
}

// ============================================================================
// Kernel 2: FUSED MLP  y = relu(BN(out @ W1)) @ W2 — two GEMM stages through
// shared memory, no g_h global round-trip.
// Block: 128-node tile, 256 threads; m = t&31 (node quad), g = t>>5 (warp group).
// Stage 1: acc[32] = 4 nodes x 16 j (group g) over sO[c][node] / sW1 broadcast.
// Transition: BN+ReLU in regs, write TRANSPOSED sH[j][node] into the smem
// region where sW1/sO lived (dead after stage 1; sync separates).
// Stage 2: 4 nodes x 8 c (group g) over sH[j][node] / sW2 broadcast.
// smem layout (ull units): [0..4096) sW1 | [4096..4224) BN | [4224..8320) sO
//                          [8320..12416) sW2 ; sH overlays [0..8192).
// Total 99328 B -> 2 blocks/SM (194 KB < 228 KB).
// ============================================================================
__global__ void __launch_bounds__(256, 2) k_mlp(
    const float* __restrict__ W1, const float* __restrict__ W2,
    const float* __restrict__ gamma, const float* __restrict__ beta,
    const float* __restrict__ mean, const float* __restrict__ var,
    float* __restrict__ y)
{
    extern __shared__ ull smF[];
    ull*   sW1 = smF;                      // 32 KB
    ull*   sS  = smF + 4096;               // 64 jpairs
    ull*   sB  = smF + 4160;               // 64 jpairs
    float* sO  = (float*)(smF + 4224);     // 32 KB  [64 c][128 node]
    ull*   sW2 = smF + 8320;               // 32 KB  [128 j][32 cpair]
    float* sH  = (float*)smF;              // 64 KB  [128 j][128 node] (overlay)

    int t  = threadIdx.x;
    int nb = blockIdx.x * 128;

    // stage weights (coalesced)
    {
        const ulonglong2* w1v = (const ulonglong2*)W1;
        const ulonglong2* w2v = (const ulonglong2*)W2;
        ulonglong2* d1 = (ulonglong2*)sW1;
        ulonglong2* d2 = (ulonglong2*)sW2;
        #pragma unroll
        for (int i = 0; i < 8; i++) {
            d1[t + 256 * i] = __ldg(w1v + t + 256 * i);
            d2[t + 256 * i] = __ldg(w2v + t + 256 * i);
        }
    }
    if (t < 64) {
        float s0 = __ldg(gamma + 2 * t)     * rsqrtf(__ldg(var + 2 * t)     + 1e-5f);
        float s1 = __ldg(gamma + 2 * t + 1) * rsqrtf(__ldg(var + 2 * t + 1) + 1e-5f);
        sS[t] = pk2(s0, s1);
        sB[t] = pk2(__ldg(beta + 2 * t)     - __ldg(mean + 2 * t)     * s0,
                    __ldg(beta + 2 * t + 1) - __ldg(mean + 2 * t + 1) * s1);
    }
    // stage O transposed: thread covers node (t&127), c-half (t>>7)
    {
        int n  = t & 127;
        int ch = (t >> 7) * 32;
        const float4* src = (const float4*)(g_out + (size_t)(nb + n) * 64 + ch);
        #pragma unroll
        for (int i = 0; i < 8; i++) {
            float4 v = __ldg(src + i);
            int c = ch + 4 * i;
            sO[(c + 0) * 128 + n] = v.x;
            sO[(c + 1) * 128 + n] = v.y;
            sO[(c + 2) * 128 + n] = v.z;
            sO[(c + 3) * 128 + n] = v.w;
        }
    }
    __syncthreads();

    int m = t & 31;    // node quad: nodes 4m..4m+3
    int g = t >> 5;    // warp group: stage1 j-group, stage2 c-group (warp-uniform)

    // ---- stage 1: layer-1 GEMM. acc[mm*8+q] = node 4m+mm, jpair g*8+q ----
    ull acc[32];
    #pragma unroll
    for (int p = 0; p < 32; p++) acc[p] = 0ULL;

    #pragma unroll 8
    for (int c = 0; c < 64; c++) {
        float4 a4 = *(const float4*)(sO + c * 128 + m * 4);
        const ulonglong2* bp = (const ulonglong2*)(sW1 + c * 64 + g * 8);
        ulonglong2 b0 = bp[0], b1 = bp[1], b2 = bp[2], b3 = bp[3];
        ull wr[8] = { b0.x, b0.y, b1.x, b1.y, b2.x, b2.y, b3.x, b3.y };
        ull ad0 = dup2(a4.x), ad1 = dup2(a4.y), ad2 = dup2(a4.z), ad3 = dup2(a4.w);
        #pragma unroll
        for (int p = 0; p < 8; p++) {
            acc[p]      = f2fma(ad0, wr[p], acc[p]);
            acc[8 + p]  = f2fma(ad1, wr[p], acc[8 + p]);
            acc[16 + p] = f2fma(ad2, wr[p], acc[16 + p]);
            acc[24 + p] = f2fma(ad3, wr[p], acc[24 + p]);
        }
    }

    // ---- BN + ReLU in registers (reads sS/sB; sW1/sO reads all done) ----
    #pragma unroll
    for (int mm = 0; mm < 4; mm++) {
        #pragma unroll
        for (int q = 0; q < 8; q++) {
            ull hb = f2fma(acc[mm * 8 + q], sS[g * 8 + q], sB[g * 8 + q]);
            float2 hv = up2(hb);
            acc[mm * 8 + q] = pk2(fmaxf(hv.x, 0.0f), fmaxf(hv.y, 0.0f));
        }
    }
    __syncthreads();   // all smem reads done before sH overlays sW1/BN/sO

    // ---- write h transposed: sH[j][node], j = g*16 + 2q (+1) ----
    #pragma unroll
    for (int q = 0; q < 8; q++) {
        float2 h0 = up2(acc[0 * 8 + q]);
        float2 h1 = up2(acc[1 * 8 + q]);
        float2 h2 = up2(acc[2 * 8 + q]);
        float2 h3 = up2(acc[3 * 8 + q]);
        *(float4*)(sH + (g * 16 + 2 * q)     * 128 + m * 4) =
            make_float4(h0.x, h1.x, h2.x, h3.x);
        *(float4*)(sH + (g * 16 + 2 * q + 1) * 128 + m * 4) =
            make_float4(h0.y, h1.y, h2.y, h3.y);
    }
    __syncthreads();

    // ---- stage 2: layer-2 GEMM. acc2[mm*4+p] = node 4m+mm, cpair g*4+p ----
    ull acc2[16];
    #pragma unroll
    for (int p = 0; p < 16; p++) acc2[p] = 0ULL;

    #pragma unroll 8
    for (int k = 0; k < 128; k++) {
        float4 a4 = *(const float4*)(sH + k * 128 + m * 4);
        const ulonglong2* bp = (const ulonglong2*)(sW2 + k * 32 + g * 4);
        ulonglong2 b0 = bp[0], b1 = bp[1];
        ull wr[4] = { b0.x, b0.y, b1.x, b1.y };
        ull ad0 = dup2(a4.x), ad1 = dup2(a4.y), ad2 = dup2(a4.z), ad3 = dup2(a4.w);
        #pragma unroll
        for (int p = 0; p < 4; p++) {
            acc2[p]      = f2fma(ad0, wr[p], acc2[p]);
            acc2[4 + p]  = f2fma(ad1, wr[p], acc2[4 + p]);
            acc2[8 + p]  = f2fma(ad2, wr[p], acc2[8 + p]);
            acc2[12 + p] = f2fma(ad3, wr[p], acc2[12 + p]);
        }
    }

    #pragma unroll
    for (int mm = 0; mm < 4; mm++) {
        ulonglong2* dst =
            (ulonglong2*)(y + (size_t)(nb + m * 4 + mm) * 64 + g * 8);
        dst[0] = make_ulonglong2(acc2[mm * 4 + 0], acc2[mm * 4 + 1]);
        dst[1] = make_ulonglong2(acc2[mm * 4 + 2], acc2[mm * 4 + 3]);
    }
}

// ============================================================================
extern "C" void kernel_launch(void* const* d_in, const int* in_sizes, int n_in,
                              void* d_out, int out_size)
{
    const float* x     = (const float*)d_in[0];
    const float* ea    = (const float*)d_in[1];
    const float* We    = (const float*)d_in[2];
    const float* W1    = (const float*)d_in[3];
    const float* W2    = (const float*)d_in[4];
    const float* gamma = (const float*)d_in[5];
    const float* beta  = (const float*)d_in[6];
    const float* mean  = (const float*)d_in[7];
    const float* var   = (const float*)d_in[8];
    const int*   eidx  = (const int*)d_in[9];   // row 0 = src
    float* y = (float*)d_out;

    (void)in_sizes; (void)n_in; (void)out_size;

    // cudaFuncSetAttribute is not a stream-associated op: safe under capture,
    // idempotent, deterministic.
    const int SMEM = 12416 * 8;   // 99328 B
    cudaFuncSetAttribute(k_mlp, cudaFuncAttributeMaxDynamicSharedMemorySize,
                         SMEM);

    k_msg<<<NN / 8, 256>>>(x, ea, We, eidx);
    k_mlp<<<NN / 128, 256, SMEM>>>(W1, W2, gamma, beta, mean, var, y);
}